// round 5
// baseline (speedup 1.0000x reference)
#include <cuda_runtime.h>
#include <cuda_bf16.h>
#include <stdint.h>

// ============================================================================
// Problem constants
// ============================================================================
#define NE      300000
#define TILE_M  128
#define NBLK    ((NE + TILE_M - 1) / TILE_M)   // 2344

// ============================================================================
// Pre-swizzled weight images (written by prep kernel each launch).
// B1 = W1 viewed as [N=256 rows][K=384], chopped into 6 K-chunks of 64,
//      each chunk an SMEM-image: row n = 128 B (64 bf16), 16B segs XOR-swizzled
//      seg' = seg ^ (n & 7).  hi/lo bf16 split.  chunk = 32 KB (16 K elems).
// B2 = W2 as [N=128][K=256], 4 chunks of 64.  chunk = 16 KB.
// ============================================================================
__device__ __nv_bfloat16 g_B1hi[98304];
__device__ __nv_bfloat16 g_B1lo[98304];
__device__ __nv_bfloat16 g_B2hi[32768];
__device__ __nv_bfloat16 g_B2lo[32768];

// ============================================================================
// SMEM layout (byte offsets, 200704 total)
//  [0,65536)       bufA: 2 buffers x (hi 16K + lo 16K)   (GEMM1 A chunks)
//                  -> during GEMM2: 2 buffers x B2 chunk (hi 16K + lo 16K)
//  [65536,196608)  bufB: 2 buffers x (hi 32K + lo 32K)   (GEMM1 B chunks)
//                  -> during GEMM2: A2 = h split: hi 4x16K @65536, lo @131072
//                  -> during LN:    staging f32 128 x 129 @65536 (66048 B)
//  [196608,...)    params: b1(1024) b2(512) gamma(512) beta(512) mu(512) rs(512)
// ============================================================================
#define OFF_B    65536
#define OFF_A2LO 131072
#define OFF_STG  65536
#define OFF_PB1  196608
#define OFF_PB2  197632
#define OFF_PG   198144
#define OFF_PBT  198656
#define OFF_MU   199168
#define OFF_RS   199680
#define SMEM_TOTAL 200704

// ============================================================================
// PTX helpers (all portable: sm_80-class instructions only)
// ============================================================================
__device__ __forceinline__ uint32_t smem_u32(const void* p) {
    uint32_t a;
    asm("{ .reg .u64 t; cvta.to.shared.u64 t, %1; cvt.u32.u64 %0, t; }" : "=r"(a) : "l"(p));
    return a;
}

__device__ __forceinline__ void ldm4(uint32_t* d, uint32_t a) {
    asm volatile("ldmatrix.sync.aligned.m8n8.x4.shared.b16 {%0,%1,%2,%3}, [%4];"
                 : "=r"(d[0]), "=r"(d[1]), "=r"(d[2]), "=r"(d[3]) : "r"(a));
}

__device__ __forceinline__ void mma16816(float* c, const uint32_t* a, const uint32_t* b) {
    asm volatile(
        "mma.sync.aligned.m16n8k16.row.col.f32.bf16.bf16.f32 "
        "{%0,%1,%2,%3}, {%4,%5,%6,%7}, {%8,%9}, {%0,%1,%2,%3};"
        : "+f"(c[0]), "+f"(c[1]), "+f"(c[2]), "+f"(c[3])
        : "r"(a[0]), "r"(a[1]), "r"(a[2]), "r"(a[3]), "r"(b[0]), "r"(b[1]));
}

__device__ __forceinline__ void cpa16(uint32_t saddr, const void* g) {
    asm volatile("cp.async.cg.shared.global [%0], [%1], 16;" :: "r"(saddr), "l"(g));
}
#define CPA_COMMIT() asm volatile("cp.async.commit_group;" ::: "memory")
#define CPA_WAIT1()  asm volatile("cp.async.wait_group 1;" ::: "memory")
#define CPA_WAIT0()  asm volatile("cp.async.wait_group 0;" ::: "memory")

__device__ __forceinline__ void pack2(float a, float b, uint32_t& h, uint32_t& l) {
    __nv_bfloat16 ha = __float2bfloat16(a), hb = __float2bfloat16(b);
    __nv_bfloat16 la = __float2bfloat16(a - __bfloat162float(ha));
    __nv_bfloat16 lb = __float2bfloat16(b - __bfloat162float(hb));
    __nv_bfloat162 hv = __halves2bfloat162(ha, hb), lv = __halves2bfloat162(la, lb);
    h = *(uint32_t*)&hv;  l = *(uint32_t*)&lv;
}

// ============================================================================
// Prep kernel: transpose + hi/lo split + chunk/swizzle weights into globals
// ============================================================================
__global__ void prep_weights_kernel(const float* __restrict__ W1,
                                    const float* __restrict__ W2) {
    int i = blockIdx.x * blockDim.x + threadIdx.x;
    if (i < 384 * 256) {                 // W1[k][n]
        int k = i >> 8, n = i & 255;
        float v = W1[i];
        __nv_bfloat16 hi = __float2bfloat16(v);
        __nv_bfloat16 lo = __float2bfloat16(v - __bfloat162float(hi));
        int c = k >> 6, kk = k & 63, seg = kk >> 3, e = kk & 7;
        int dst = c * 16384 + n * 64 + ((seg ^ (n & 7)) << 3) + e;
        g_B1hi[dst] = hi;  g_B1lo[dst] = lo;
    }
    if (i < 256 * 128) {                 // W2[k][n]
        int k = i >> 7, n = i & 127;
        float v = W2[i];
        __nv_bfloat16 hi = __float2bfloat16(v);
        __nv_bfloat16 lo = __float2bfloat16(v - __bfloat162float(hi));
        int c = k >> 6, kk = k & 63, seg = kk >> 3, e = kk & 7;
        int dst = c * 8192 + n * 64 + ((seg ^ (n & 7)) << 3) + e;
        g_B2hi[dst] = hi;  g_B2lo[dst] = lo;
    }
}

// ============================================================================
// Main fused kernel. CTA = 128 edges, 256 threads (8 warps).
// GEMM1: out 128x256, warp tile 32x128 (warps: rg = wid&3, cg = wid>>2)
// GEMM2: out 128x128, warp tile 32x64
// ============================================================================
__global__ __launch_bounds__(256, 1)
void edge_mlp_kernel(const float* __restrict__ node_attr,
                     const float* __restrict__ edge_attr,
                     const int*   __restrict__ eidx,
                     const float* __restrict__ b1,
                     const float* __restrict__ b2,
                     const float* __restrict__ gamma,
                     const float* __restrict__ beta,
                     float*       __restrict__ out) {
    extern __shared__ char smem[];
    const uint32_t sb = smem_u32(smem);
    const int tid = threadIdx.x;
    const int wid = tid >> 5;
    const int lid = tid & 31;
    const int rg  = wid & 3;          // row group (32 rows)
    const int cg  = wid >> 2;         // col group
    const int e0  = blockIdx.x * TILE_M;
    const int valid = min(TILE_M, NE - e0);

    const int* sidx = eidx;
    const int* ridx = eidx + NE;

    float* b1s  = (float*)(smem + OFF_PB1);
    float* b2s  = (float*)(smem + OFF_PB2);
    float* gams = (float*)(smem + OFF_PG);
    float* bets = (float*)(smem + OFF_PBT);
    float* muA  = (float*)(smem + OFF_MU);
    float* rsA  = (float*)(smem + OFF_RS);
    b1s[tid] = b1[tid];
    if (tid < 128) { b2s[tid] = b2[tid]; gams[tid] = gamma[tid]; bets[tid] = beta[tid]; }

    // ---- gather + convert one A chunk into bufA[buf] ------------------------
    auto gather_sts = [&](int kc, int buf) {
        uint32_t dst = (uint32_t)buf * 32768u;
        #pragma unroll
        for (int i = 0; i < 4; i++) {
            int task = tid + (i << 8);          // 0..1023
            int r = task >> 3, seg = task & 7;
            int e = e0 + r;  if (e >= NE) e = NE - 1;
            int off = ((kc & 1) << 6) + (seg << 3);
            const float* src;
            if (kc < 2)      src = node_attr + (size_t)sidx[e] * 128 + off;
            else if (kc < 4) src = node_attr + (size_t)ridx[e] * 128 + off;
            else             src = edge_attr + (size_t)e * 128 + off;
            float4 x0 = ((const float4*)src)[0];
            float4 x1 = ((const float4*)src)[1];
            uint32_t h[4], l[4];
            pack2(x0.x, x0.y, h[0], l[0]);  pack2(x0.z, x0.w, h[1], l[1]);
            pack2(x1.x, x1.y, h[2], l[2]);  pack2(x1.z, x1.w, h[3], l[3]);
            uint32_t o = dst + (uint32_t)(r * 128 + ((seg ^ (r & 7)) << 4));
            *(uint4*)(smem + o)         = make_uint4(h[0], h[1], h[2], h[3]);
            *(uint4*)(smem + o + 16384) = make_uint4(l[0], l[1], l[2], l[3]);
        }
    };

    auto copyB1 = [&](int c, int buf) {
        const char* sh = (const char*)g_B1hi + (size_t)c * 32768;
        const char* sl = (const char*)g_B1lo + (size_t)c * 32768;
        uint32_t dh = sb + OFF_B + (uint32_t)buf * 65536u;
        #pragma unroll
        for (int i = 0; i < 8; i++) {
            int t = (tid + (i << 8)) << 4;      // byte offset, 16B lines
            cpa16(dh + t, sh + t);
            cpa16(dh + 32768 + t, sl + t);
        }
    };

    auto copyB2 = [&](int c, int buf) {
        const char* sh = (const char*)g_B2hi + (size_t)c * 16384;
        const char* sl = (const char*)g_B2lo + (size_t)c * 16384;
        uint32_t dh = sb + (uint32_t)buf * 32768u;
        #pragma unroll
        for (int i = 0; i < 4; i++) {
            int t = (tid + (i << 8)) << 4;
            cpa16(dh + t, sh + t);
            cpa16(dh + 16384 + t, sl + t);
        }
    };

    // ------------------------------------------------------------------------
    // GEMM1: acc1[2][16][4]  (warp: rows rg*32+[0,32), cols cg*128+[0,128))
    // ------------------------------------------------------------------------
    float acc1[2][16][4];
    #pragma unroll
    for (int a = 0; a < 2; a++)
        #pragma unroll
        for (int b = 0; b < 16; b++)
            #pragma unroll
            for (int c = 0; c < 4; c++) acc1[a][b][c] = 0.0f;

    // prime: B1 chunk 0 (async) + A chunk 0 (sync)
    copyB1(0, 0);
    CPA_COMMIT();
    gather_sts(0, 0);

    for (int kc = 0; kc < 6; kc++) {
        const int cur = kc & 1, nxt = cur ^ 1;
        if (kc < 5) { gather_sts(kc + 1, nxt); copyB1(kc + 1, nxt); }
        else        { copyB2(0, 0); }           // prefetch first B2 chunk
        CPA_COMMIT();
        CPA_WAIT1();
        __syncthreads();                        // chunk kc resident + visible

        const uint32_t aHi = sb + (uint32_t)cur * 32768u;
        const uint32_t aLo = aHi + 16384u;
        const uint32_t bHi = sb + OFF_B + (uint32_t)cur * 65536u;
        const uint32_t bLo = bHi + 32768u;

        #pragma unroll
        for (int ks = 0; ks < 4; ks++) {
            uint32_t Ah[2][4], Al[2][4];
            #pragma unroll
            for (int mg = 0; mg < 2; mg++) {
                int row = rg * 32 + mg * 16 + (lid & 15);
                int seg = 2 * ks + (lid >> 4);
                uint32_t o = (uint32_t)(row * 128 + ((seg ^ (row & 7)) << 4));
                ldm4(Ah[mg], aHi + o);
                ldm4(Al[mg], aLo + o);
            }
            #pragma unroll
            for (int nh = 0; nh < 2; nh++) {
                uint32_t Bh[4][4], Bl[4][4];
                #pragma unroll
                for (int g = 0; g < 4; g++) {
                    int n = cg * 128 + nh * 64 + g * 16 + ((lid >> 4) << 3) + (lid & 7);
                    int seg = 2 * ks + ((lid >> 3) & 1);
                    uint32_t o = (uint32_t)(n * 128 + ((seg ^ (n & 7)) << 4));
                    ldm4(Bh[g], bHi + o);
                    ldm4(Bl[g], bLo + o);
                }
                #pragma unroll
                for (int mg = 0; mg < 2; mg++)
                    #pragma unroll
                    for (int g = 0; g < 4; g++)
                        #pragma unroll
                        for (int h = 0; h < 2; h++) {
                            float* c = acc1[mg][nh * 8 + g * 2 + h];
                            mma16816(c, Ah[mg], &Bh[g][2 * h]);
                            mma16816(c, Ah[mg], &Bl[g][2 * h]);
                            mma16816(c, Al[mg], &Bh[g][2 * h]);
                        }
            }
        }
        __syncthreads();                        // protect buffers for next iter
    }

    // ------------------------------------------------------------------------
    // Epilogue 1: h = relu(acc1 + b1) -> split -> A2 image (bufB region)
    // ------------------------------------------------------------------------
    #pragma unroll
    for (int mg = 0; mg < 2; mg++)
        #pragma unroll
        for (int nt = 0; nt < 16; nt++) {
            int coln = cg * 128 + nt * 8 + 2 * (lid & 3);
            float bb0 = b1s[coln], bb1 = b1s[coln + 1];
            int c = coln >> 6, kk = coln & 63, seg = kk >> 3, ee = kk & 7;
            #pragma unroll
            for (int h = 0; h < 2; h++) {
                int row = rg * 32 + mg * 16 + (lid >> 2) + h * 8;
                float v0 = fmaxf(acc1[mg][nt][2 * h]     + bb0, 0.0f);
                float v1 = fmaxf(acc1[mg][nt][2 * h + 1] + bb1, 0.0f);
                uint32_t hi, lo;
                pack2(v0, v1, hi, lo);
                uint32_t o = (uint32_t)(row * 128 + ((seg ^ (row & 7)) << 4) + ee * 2);
                *(uint32_t*)(smem + OFF_B    + c * 16384 + o) = hi;
                *(uint32_t*)(smem + OFF_A2LO + c * 16384 + o) = lo;
            }
        }

    // ------------------------------------------------------------------------
    // GEMM2: acc2[2][8][4]  (warp: rows rg*32, cols cg*64)
    // ------------------------------------------------------------------------
    float acc2[2][8][4];
    #pragma unroll
    for (int a = 0; a < 2; a++)
        #pragma unroll
        for (int b = 0; b < 8; b++)
            #pragma unroll
            for (int c = 0; c < 4; c++) acc2[a][b][c] = 0.0f;

    for (int kc = 0; kc < 4; kc++) {
        if (kc < 3) copyB2(kc + 1, (kc + 1) & 1);
        CPA_COMMIT();
        if (kc < 3) CPA_WAIT1(); else CPA_WAIT0();
        __syncthreads();                        // B2[kc] + (kc==0: A2) visible

        const uint32_t aHi = sb + OFF_B    + (uint32_t)kc * 16384u;
        const uint32_t aLo = sb + OFF_A2LO + (uint32_t)kc * 16384u;
        const uint32_t bHi = sb + (uint32_t)(kc & 1) * 32768u;
        const uint32_t bLo = bHi + 16384u;

        #pragma unroll
        for (int ks = 0; ks < 4; ks++) {
            uint32_t Ah[2][4], Al[2][4];
            #pragma unroll
            for (int mg = 0; mg < 2; mg++) {
                int row = rg * 32 + mg * 16 + (lid & 15);
                int seg = 2 * ks + (lid >> 4);
                uint32_t o = (uint32_t)(row * 128 + ((seg ^ (row & 7)) << 4));
                ldm4(Ah[mg], aHi + o);
                ldm4(Al[mg], aLo + o);
            }
            uint32_t Bh[4][4], Bl[4][4];
            #pragma unroll
            for (int g = 0; g < 4; g++) {
                int n = cg * 64 + g * 16 + ((lid >> 4) << 3) + (lid & 7);
                int seg = 2 * ks + ((lid >> 3) & 1);
                uint32_t o = (uint32_t)(n * 128 + ((seg ^ (n & 7)) << 4));
                ldm4(Bh[g], bHi + o);
                ldm4(Bl[g], bLo + o);
            }
            #pragma unroll
            for (int mg = 0; mg < 2; mg++)
                #pragma unroll
                for (int g = 0; g < 4; g++)
                    #pragma unroll
                    for (int h = 0; h < 2; h++) {
                        float* c = acc2[mg][g * 2 + h];
                        mma16816(c, Ah[mg], &Bh[g][2 * h]);
                        mma16816(c, Ah[mg], &Bl[g][2 * h]);
                        mma16816(c, Al[mg], &Bh[g][2 * h]);
                    }
        }
        __syncthreads();
    }

    // ------------------------------------------------------------------------
    // Epilogue 2: staging = acc2 + b2 (f32, stride 129), then LayerNorm
    // ------------------------------------------------------------------------
    float* stg = (float*)(smem + OFF_STG);
    #pragma unroll
    for (int mg = 0; mg < 2; mg++)
        #pragma unroll
        for (int nt = 0; nt < 8; nt++) {
            int coln = cg * 64 + nt * 8 + 2 * (lid & 3);
            float bb0 = b2s[coln], bb1 = b2s[coln + 1];
            #pragma unroll
            for (int h = 0; h < 2; h++) {
                int row = rg * 32 + mg * 16 + (lid >> 2) + h * 8;
                stg[row * 129 + coln]     = acc2[mg][nt][2 * h]     + bb0;
                stg[row * 129 + coln + 1] = acc2[mg][nt][2 * h + 1] + bb1;
            }
        }
    __syncthreads();

    if (tid < 128) {
        const float* rp = stg + tid * 129;
        float s = 0.0f, q = 0.0f;
        #pragma unroll 8
        for (int i = 0; i < 128; i++) { float v = rp[i]; s += v; q += v * v; }
        float mu = s * (1.0f / 128.0f);
        float var = fmaxf(q * (1.0f / 128.0f) - mu * mu, 0.0f);
        muA[tid] = mu;
        rsA[tid] = rsqrtf(var + 1e-5f);
    }
    __syncthreads();

    for (int i = tid; i < 4096; i += 256) {
        int r = i >> 5, c4 = (i & 31) << 2;
        if (r < valid) {
            float mu = muA[r], rs = rsA[r];
            const float* rp = stg + r * 129;
            float4 o;
            o.x = (rp[c4]     - mu) * rs * gams[c4]     + bets[c4];
            o.y = (rp[c4 + 1] - mu) * rs * gams[c4 + 1] + bets[c4 + 1];
            o.z = (rp[c4 + 2] - mu) * rs * gams[c4 + 2] + bets[c4 + 2];
            o.w = (rp[c4 + 3] - mu) * rs * gams[c4 + 3] + bets[c4 + 3];
            *(float4*)(out + (size_t)(e0 + r) * 128 + c4) = o;
        }
    }
}

// ============================================================================
// Launch
// ============================================================================
extern "C" void kernel_launch(void* const* d_in, const int* in_sizes, int n_in,
                              void* d_out, int out_size) {
    const float* node_attr = (const float*)d_in[0];
    const float* edge_attr = (const float*)d_in[1];
    const int*   eidx      = (const int*)d_in[2];
    const float* W1        = (const float*)d_in[3];
    const float* b1        = (const float*)d_in[4];
    const float* W2        = (const float*)d_in[5];
    const float* b2        = (const float*)d_in[6];
    const float* gamma     = (const float*)d_in[7];
    const float* beta      = (const float*)d_in[8];
    float* out = (float*)d_out;

    cudaFuncSetAttribute(edge_mlp_kernel,
                         cudaFuncAttributeMaxDynamicSharedMemorySize, SMEM_TOTAL);

    prep_weights_kernel<<<(384 * 256 + 255) / 256, 256>>>(W1, W2);
    edge_mlp_kernel<<<NBLK, 256, SMEM_TOTAL>>>(node_attr, edge_attr, eidx,
                                               b1, b2, gamma, beta, out);
}

// round 7
// speedup vs baseline: 1.8982x; 1.8982x over previous
#include <cuda_runtime.h>
#include <cuda_fp16.h>
#include <stdint.h>

// ============================================================================
// Problem constants
// ============================================================================
#define NE      300000
#define TILE_M  128
#define NBLK    ((NE + TILE_M - 1) / TILE_M)   // 2344

// ============================================================================
// Pre-swizzled fp16 weight images (written by prep kernel each launch).
// B1 = W1 as [N=256 rows][K=384], 6 K-chunks of 64; row = 128 B (64 fp16),
//      16B segs XOR-swizzled seg' = seg ^ (n & 7). chunk = 32 KB.
// B2 = W2 as [N=128][K=256], 4 chunks of 64. chunk = 16 KB.
// ============================================================================
__device__ __half g_B1h[98304];
__device__ __half g_B2h[32768];

// ============================================================================
// SMEM layout (bytes)
//  [0, 98304)        A full: 6 chunks x 16 KB (128 rows x 64 fp16, swizzled)
//                    GEMM2: A2 (h) chunks 0-3 at [0,65536); bufB2 2x16K at
//                    [65536, 98304)
//  [98304, 163840)   bufB1: 2 x 32 KB (GEMM1 B chunks)
//  [98304, 164352)   LN staging f32 128 x 129 (reuses dead bufB1)
//  [164352, 167936)  params: b1(1K) b2(512) gamma(512) beta(512) mu(512) rs(512)
// ============================================================================
#define OFF_B2   65536
#define OFF_B1   98304
#define OFF_STG  98304
#define OFF_PB1  164352
#define OFF_PB2  165376
#define OFF_PG   165888
#define OFF_PBT  166400
#define OFF_MU   166912
#define OFF_RS   167424
#define SMEM_TOTAL 167936

// ============================================================================
// PTX helpers (sm_80-portable only; no tcgen05 on this toolchain target)
// ============================================================================
__device__ __forceinline__ uint32_t smem_u32(const void* p) {
    uint32_t a;
    asm("{ .reg .u64 t; cvta.to.shared.u64 t, %1; cvt.u32.u64 %0, t; }" : "=r"(a) : "l"(p));
    return a;
}

__device__ __forceinline__ void ldm4(uint32_t* d, uint32_t a) {
    asm volatile("ldmatrix.sync.aligned.m8n8.x4.shared.b16 {%0,%1,%2,%3}, [%4];"
                 : "=r"(d[0]), "=r"(d[1]), "=r"(d[2]), "=r"(d[3]) : "r"(a));
}

__device__ __forceinline__ void mma16816(float* c, const uint32_t* a, const uint32_t* b) {
    asm volatile(
        "mma.sync.aligned.m16n8k16.row.col.f32.f16.f16.f32 "
        "{%0,%1,%2,%3}, {%4,%5,%6,%7}, {%8,%9}, {%0,%1,%2,%3};"
        : "+f"(c[0]), "+f"(c[1]), "+f"(c[2]), "+f"(c[3])
        : "r"(a[0]), "r"(a[1]), "r"(a[2]), "r"(a[3]), "r"(b[0]), "r"(b[1]));
}

__device__ __forceinline__ void cpa16(uint32_t saddr, const void* g) {
    asm volatile("cp.async.cg.shared.global [%0], [%1], 16;" :: "r"(saddr), "l"(g));
}
#define CPA_COMMIT() asm volatile("cp.async.commit_group;" ::: "memory")
#define CPA_WAIT1()  asm volatile("cp.async.wait_group 1;" ::: "memory")
#define CPA_WAIT0()  asm volatile("cp.async.wait_group 0;" ::: "memory")

__device__ __forceinline__ uint32_t packh2(float a, float b) {
    __half2 h = __floats2half2_rn(a, b);
    return *(uint32_t*)&h;
}

// ============================================================================
// Prep kernel: transpose + fp16 round + chunk/swizzle weights
// ============================================================================
__global__ void prep_weights_kernel(const float* __restrict__ W1,
                                    const float* __restrict__ W2) {
    int i = blockIdx.x * blockDim.x + threadIdx.x;
    if (i < 384 * 256) {                 // W1[k][n]
        int k = i >> 8, n = i & 255;
        int c = k >> 6, kk = k & 63, seg = kk >> 3, e = kk & 7;
        g_B1h[c * 16384 + n * 64 + ((seg ^ (n & 7)) << 3) + e] = __float2half(W1[i]);
    }
    if (i < 256 * 128) {                 // W2[k][n]
        int k = i >> 7, n = i & 127;
        int c = k >> 6, kk = k & 63, seg = kk >> 3, e = kk & 7;
        g_B2h[c * 8192 + n * 64 + ((seg ^ (n & 7)) << 3) + e] = __float2half(W2[i]);
    }
}

// ============================================================================
// Main fused kernel. CTA = 128 edges, 256 threads (8 warps).
// GEMM1: out 128x256, warp tile 32x128 (rg = wid&3, cg = wid>>2)
// GEMM2: out 128x128, warp tile 32x64
// ============================================================================
__global__ __launch_bounds__(256, 1)
void edge_mlp_kernel(const float* __restrict__ node_attr,
                     const float* __restrict__ edge_attr,
                     const int*   __restrict__ eidx,
                     const float* __restrict__ b1,
                     const float* __restrict__ b2,
                     const float* __restrict__ gamma,
                     const float* __restrict__ beta,
                     float*       __restrict__ out) {
    extern __shared__ char smem[];
    const uint32_t sb = smem_u32(smem);
    const int tid = threadIdx.x;
    const int wid = tid >> 5;
    const int lid = tid & 31;
    const int rg  = wid & 3;
    const int cg  = wid >> 2;
    const int e0  = blockIdx.x * TILE_M;
    const int valid = min(TILE_M, NE - e0);

    const int* sidx = eidx;
    const int* ridx = eidx + NE;

    float* b1s  = (float*)(smem + OFF_PB1);
    float* b2s  = (float*)(smem + OFF_PB2);
    float* gams = (float*)(smem + OFF_PG);
    float* bets = (float*)(smem + OFF_PBT);
    float* muA  = (float*)(smem + OFF_MU);
    float* rsA  = (float*)(smem + OFF_RS);
    b1s[tid] = b1[tid];
    if (tid < 128) { b2s[tid] = b2[tid]; gams[tid] = gamma[tid]; bets[tid] = beta[tid]; }

    // ---- staged gather: chunk kc = cols [(kc&1)*64, +64) of source kc>>1 ----
    // per chunk: 1024 tasks (128 rows x 8 segs), 4 per thread, 8 f32 each
    float4 st[8];
    auto gather_ld = [&](int kc) {
        #pragma unroll
        for (int i = 0; i < 4; i++) {
            int task = tid + (i << 8);
            int r = task >> 3, seg = task & 7;
            int e = e0 + r;  if (e >= NE) e = NE - 1;
            int off = ((kc & 1) << 6) + (seg << 3);
            const float* src;
            if (kc < 2)      src = node_attr + (size_t)sidx[e] * 128 + off;
            else if (kc < 4) src = node_attr + (size_t)ridx[e] * 128 + off;
            else             src = edge_attr + (size_t)e * 128 + off;
            st[2 * i]     = ((const float4*)src)[0];
            st[2 * i + 1] = ((const float4*)src)[1];
        }
    };
    auto gather_st = [&](int kc) {
        #pragma unroll
        for (int i = 0; i < 4; i++) {
            int task = tid + (i << 8);
            int r = task >> 3, seg = task & 7;
            float4 x0 = st[2 * i], x1 = st[2 * i + 1];
            uint4 p = make_uint4(packh2(x0.x, x0.y), packh2(x0.z, x0.w),
                                 packh2(x1.x, x1.y), packh2(x1.z, x1.w));
            uint32_t o = (uint32_t)(kc * 16384 + r * 128 + ((seg ^ (r & 7)) << 4));
            *(uint4*)(smem + o) = p;
        }
    };

    auto copyB1 = [&](int c, int buf) {
        const char* s = (const char*)g_B1h + (size_t)c * 32768;
        uint32_t d = sb + OFF_B1 + (uint32_t)buf * 32768u;
        #pragma unroll
        for (int i = 0; i < 8; i++) {
            int t = (tid + (i << 8)) << 4;
            cpa16(d + t, s + t);
        }
    };
    auto copyB2 = [&](int c, int buf) {
        const char* s = (const char*)g_B2h + (size_t)c * 16384;
        uint32_t d = sb + OFF_B2 + (uint32_t)buf * 16384u;
        #pragma unroll
        for (int i = 0; i < 4; i++) {
            int t = (tid + (i << 8)) << 4;
            cpa16(d + t, s + t);
        }
    };

    // ------------------------------------------------------------------------
    // GEMM1: acc1[2][16][4]  (warp: rows rg*32+[0,32), cols cg*128+[0,128))
    // ------------------------------------------------------------------------
    float acc1[2][16][4];
    #pragma unroll
    for (int a = 0; a < 2; a++)
        #pragma unroll
        for (int b = 0; b < 16; b++)
            #pragma unroll
            for (int c = 0; c < 4; c++) acc1[a][b][c] = 0.0f;

    copyB1(0, 0); CPA_COMMIT();
    copyB1(1, 1); CPA_COMMIT();
    gather_ld(0); gather_st(0);
    gather_ld(1); gather_st(1);

    for (int kc = 0; kc < 6; kc++) {
        if (kc < 4) gather_ld(kc + 2);          // LDGs in flight during MMAs
        CPA_WAIT1();
        __syncthreads();                        // chunk kc (A + B1) visible

        const uint32_t aBase = sb + (uint32_t)kc * 16384u;
        const uint32_t bBase = sb + OFF_B1 + (uint32_t)(kc & 1) * 32768u;

        #pragma unroll
        for (int ks = 0; ks < 4; ks++) {
            uint32_t Ah[2][4];
            #pragma unroll
            for (int mg = 0; mg < 2; mg++) {
                int row = rg * 32 + mg * 16 + (lid & 15);
                int seg = 2 * ks + (lid >> 4);
                ldm4(Ah[mg], aBase + (uint32_t)(row * 128 + ((seg ^ (row & 7)) << 4)));
            }
            #pragma unroll
            for (int nh = 0; nh < 2; nh++) {
                uint32_t Bh[4][4];
                #pragma unroll
                for (int g = 0; g < 4; g++) {
                    int n = cg * 128 + nh * 64 + g * 16 + ((lid >> 4) << 3) + (lid & 7);
                    int seg = 2 * ks + ((lid >> 3) & 1);
                    ldm4(Bh[g], bBase + (uint32_t)(n * 128 + ((seg ^ (n & 7)) << 4)));
                }
                #pragma unroll
                for (int mg = 0; mg < 2; mg++)
                    #pragma unroll
                    for (int g = 0; g < 4; g++)
                        #pragma unroll
                        for (int h = 0; h < 2; h++)
                            mma16816(acc1[mg][nh * 8 + g * 2 + h], Ah[mg], &Bh[g][2 * h]);
            }
        }
        if (kc < 4) gather_st(kc + 2);          // fill A chunk kc+2
        __syncthreads();                        // protect B buffer reuse
        if (kc < 4)      { copyB1(kc + 2, kc & 1); CPA_COMMIT(); }
        else if (kc == 4){ copyB2(0, 0);           CPA_COMMIT(); }
        else             { copyB2(1, 1);           CPA_COMMIT(); }
    }

    // ------------------------------------------------------------------------
    // Epilogue 1: h = relu(acc1 + b1) -> fp16 -> A2 image at [0, 64K)
    // ------------------------------------------------------------------------
    #pragma unroll
    for (int mg = 0; mg < 2; mg++)
        #pragma unroll
        for (int nt = 0; nt < 16; nt++) {
            int coln = cg * 128 + nt * 8 + 2 * (lid & 3);
            float bb0 = b1s[coln], bb1 = b1s[coln + 1];
            int c = coln >> 6, kk = coln & 63, seg = kk >> 3, ee = kk & 7;
            #pragma unroll
            for (int h = 0; h < 2; h++) {
                int row = rg * 32 + mg * 16 + (lid >> 2) + h * 8;
                float v0 = fmaxf(acc1[mg][nt][2 * h]     + bb0, 0.0f);
                float v1 = fmaxf(acc1[mg][nt][2 * h + 1] + bb1, 0.0f);
                uint32_t o = (uint32_t)(row * 128 + ((seg ^ (row & 7)) << 4) + ee * 2);
                *(uint32_t*)(smem + c * 16384 + o) = packh2(v0, v1);
            }
        }

    // ------------------------------------------------------------------------
    // GEMM2: acc2[2][8][4]  (warp: rows rg*32, cols cg*64)
    // ------------------------------------------------------------------------
    float acc2[2][8][4];
    #pragma unroll
    for (int a = 0; a < 2; a++)
        #pragma unroll
        for (int b = 0; b < 8; b++)
            #pragma unroll
            for (int c = 0; c < 4; c++) acc2[a][b][c] = 0.0f;

    for (int kc = 0; kc < 4; kc++) {
        if (kc < 3) CPA_WAIT1(); else CPA_WAIT0();
        __syncthreads();                        // B2[kc] + (kc==0: A2) visible

        const uint32_t aBase = sb + (uint32_t)kc * 16384u;
        const uint32_t bBase = sb + OFF_B2 + (uint32_t)(kc & 1) * 16384u;

        #pragma unroll
        for (int ks = 0; ks < 4; ks++) {
            uint32_t Ah[2][4];
            #pragma unroll
            for (int mg = 0; mg < 2; mg++) {
                int row = rg * 32 + mg * 16 + (lid & 15);
                int seg = 2 * ks + (lid >> 4);
                ldm4(Ah[mg], aBase + (uint32_t)(row * 128 + ((seg ^ (row & 7)) << 4)));
            }
            uint32_t Bh[4][4];
            #pragma unroll
            for (int g = 0; g < 4; g++) {
                int n = cg * 64 + g * 16 + ((lid >> 4) << 3) + (lid & 7);
                int seg = 2 * ks + ((lid >> 3) & 1);
                ldm4(Bh[g], bBase + (uint32_t)(n * 128 + ((seg ^ (n & 7)) << 4)));
            }
            #pragma unroll
            for (int mg = 0; mg < 2; mg++)
                #pragma unroll
                for (int g = 0; g < 4; g++)
                    #pragma unroll
                    for (int h = 0; h < 2; h++)
                        mma16816(acc2[mg][g * 2 + h], Ah[mg], &Bh[g][2 * h]);
        }
        __syncthreads();
        if (kc < 2) { copyB2(kc + 2, kc & 1); CPA_COMMIT(); }
    }

    // ------------------------------------------------------------------------
    // Epilogue 2: staging = acc2 + b2 (f32, stride 129), then LayerNorm
    // ------------------------------------------------------------------------
    float* stg = (float*)(smem + OFF_STG);
    #pragma unroll
    for (int mg = 0; mg < 2; mg++)
        #pragma unroll
        for (int nt = 0; nt < 8; nt++) {
            int coln = cg * 64 + nt * 8 + 2 * (lid & 3);
            float bb0 = b2s[coln], bb1 = b2s[coln + 1];
            #pragma unroll
            for (int h = 0; h < 2; h++) {
                int row = rg * 32 + mg * 16 + (lid >> 2) + h * 8;
                stg[row * 129 + coln]     = acc2[mg][nt][2 * h]     + bb0;
                stg[row * 129 + coln + 1] = acc2[mg][nt][2 * h + 1] + bb1;
            }
        }
    __syncthreads();

    if (tid < 128) {
        const float* rp = stg + tid * 129;
        float s = 0.0f, q = 0.0f;
        #pragma unroll 8
        for (int i = 0; i < 128; i++) { float v = rp[i]; s += v; q += v * v; }
        float mu = s * (1.0f / 128.0f);
        float var = fmaxf(q * (1.0f / 128.0f) - mu * mu, 0.0f);
        muA[tid] = mu;
        rsA[tid] = rsqrtf(var + 1e-5f);
    }
    __syncthreads();

    for (int i = tid; i < 4096; i += 256) {
        int r = i >> 5, c4 = (i & 31) << 2;
        if (r < valid) {
            float mu = muA[r], rs = rsA[r];
            const float* rp = stg + r * 129;
            float4 o;
            o.x = (rp[c4]     - mu) * rs * gams[c4]     + bets[c4];
            o.y = (rp[c4 + 1] - mu) * rs * gams[c4 + 1] + bets[c4 + 1];
            o.z = (rp[c4 + 2] - mu) * rs * gams[c4 + 2] + bets[c4 + 2];
            o.w = (rp[c4 + 3] - mu) * rs * gams[c4 + 3] + bets[c4 + 3];
            *(float4*)(out + (size_t)(e0 + r) * 128 + c4) = o;
        }
    }
}

// ============================================================================
// Launch
// ============================================================================
extern "C" void kernel_launch(void* const* d_in, const int* in_sizes, int n_in,
                              void* d_out, int out_size) {
    const float* node_attr = (const float*)d_in[0];
    const float* edge_attr = (const float*)d_in[1];
    const int*   eidx      = (const int*)d_in[2];
    const float* W1        = (const float*)d_in[3];
    const float* b1        = (const float*)d_in[4];
    const float* W2        = (const float*)d_in[5];
    const float* b2        = (const float*)d_in[6];
    const float* gamma     = (const float*)d_in[7];
    const float* beta      = (const float*)d_in[8];
    float* out = (float*)d_out;

    cudaFuncSetAttribute(edge_mlp_kernel,
                         cudaFuncAttributeMaxDynamicSharedMemorySize, SMEM_TOTAL);

    prep_weights_kernel<<<(384 * 256 + 255) / 256, 256>>>(W1, W2);
    edge_mlp_kernel<<<NBLK, 256, SMEM_TOTAL>>>(node_attr, edge_attr, eidx,
                                               b1, b2, gamma, beta, out);
}

// round 9
// speedup vs baseline: 2.0552x; 1.0827x over previous
#include <cuda_runtime.h>
#include <cuda_fp16.h>
#include <stdint.h>

// ============================================================================
// Problem constants
// ============================================================================
#define NE      300000
#define TILE_M  64
#define NBLK    ((NE + TILE_M - 1) / TILE_M)   // 4688

// ============================================================================
// Pre-swizzled fp16 weight images (written by prep kernel each launch).
// B1 = W1 as [N=256 rows][K=384], 6 K-chunks of 64; row = 128 B (64 fp16),
//      16B segs XOR-swizzled seg' = seg ^ (n & 7). chunk = 32 KB.
// B2 = W2 as [N=128][K=256], 4 chunks of 64. chunk = 16 KB.
// ============================================================================
__device__ __half g_B1h[98304];
__device__ __half g_B2h[32768];

// ============================================================================
// SMEM layout (bytes), 84480 total per CTA -> 2 CTAs/SM (168960 <= 228K)
//  [0, 16384)      A1 double buffer (2 x 8K = 64 rows x 128B).  After GEMM1:
//                  LN partials: part_s[64*4] @0, part_q @1024, mu @2048, rs @2304
//  [16384, 81920)  B1 double buffer (2 x 32K).  Overlays after use:
//                    B2 buf0 [16384,32768)  (B1 buf0 lower, dead after kc=4)
//                    B2 buf1 [32768,49152)  (B1 buf0 upper, dead after kc=4)
//                    A2 (h)  [49152,81920)  (B1 buf1, dead after kc=5)
//  [81920, 84480)  params: b1(1K) b2(512) gamma(512) beta(512)
// ============================================================================
#define OFF_LNS  0
#define OFF_LNQ  1024
#define OFF_MU   2048
#define OFF_RS   2304
#define OFF_B1   16384
#define OFF_B2   16384
#define OFF_A2   49152
#define OFF_PB1  81920
#define OFF_PB2  82944
#define OFF_PG   83456
#define OFF_PBT  83968
#define SMEM_TOTAL 84480

// ============================================================================
// PTX helpers (sm_80-portable only; tcgen05 rejected by this toolchain target)
// ============================================================================
__device__ __forceinline__ uint32_t smem_u32(const void* p) {
    uint32_t a;
    asm("{ .reg .u64 t; cvta.to.shared.u64 t, %1; cvt.u32.u64 %0, t; }" : "=r"(a) : "l"(p));
    return a;
}

__device__ __forceinline__ void ldm4(uint32_t* d, uint32_t a) {
    asm volatile("ldmatrix.sync.aligned.m8n8.x4.shared.b16 {%0,%1,%2,%3}, [%4];"
                 : "=r"(d[0]), "=r"(d[1]), "=r"(d[2]), "=r"(d[3]) : "r"(a));
}

__device__ __forceinline__ void mma16816(float* c, const uint32_t* a, const uint32_t* b) {
    asm volatile(
        "mma.sync.aligned.m16n8k16.row.col.f32.f16.f16.f32 "
        "{%0,%1,%2,%3}, {%4,%5,%6,%7}, {%8,%9}, {%0,%1,%2,%3};"
        : "+f"(c[0]), "+f"(c[1]), "+f"(c[2]), "+f"(c[3])
        : "r"(a[0]), "r"(a[1]), "r"(a[2]), "r"(a[3]), "r"(b[0]), "r"(b[1]));
}

__device__ __forceinline__ void cpa16(uint32_t saddr, const void* g) {
    asm volatile("cp.async.cg.shared.global [%0], [%1], 16;" :: "r"(saddr), "l"(g));
}
#define CPA_COMMIT() asm volatile("cp.async.commit_group;" ::: "memory")
#define CPA_WAIT1()  asm volatile("cp.async.wait_group 1;" ::: "memory")
#define CPA_WAIT0()  asm volatile("cp.async.wait_group 0;" ::: "memory")

__device__ __forceinline__ uint32_t packh2(float a, float b) {
    __half2 h = __floats2half2_rn(a, b);
    return *(uint32_t*)&h;
}

// ============================================================================
// Prep kernel: transpose + fp16 round + chunk/swizzle weights
// ============================================================================
__global__ void prep_weights_kernel(const float* __restrict__ W1,
                                    const float* __restrict__ W2) {
    int i = blockIdx.x * blockDim.x + threadIdx.x;
    if (i < 384 * 256) {                 // W1[k][n]
        int k = i >> 8, n = i & 255;
        int c = k >> 6, kk = k & 63, seg = kk >> 3, e = kk & 7;
        g_B1h[c * 16384 + n * 64 + ((seg ^ (n & 7)) << 3) + e] = __float2half(W1[i]);
    }
    if (i < 256 * 128) {                 // W2[k][n]
        int k = i >> 7, n = i & 127;
        int c = k >> 6, kk = k & 63, seg = kk >> 3, e = kk & 7;
        g_B2h[c * 8192 + n * 64 + ((seg ^ (n & 7)) << 3) + e] = __float2half(W2[i]);
    }
}

// ============================================================================
// Main fused kernel. CTA = 64 edges, 256 threads (8 warps), 2 CTAs/SM.
// GEMM1: out 64x256, warp tile 32x64  (rg = wid&1, cg = wid>>1)
// GEMM2: out 64x128, warp tile 32x32
// ============================================================================
__global__ __launch_bounds__(256, 2)
void edge_mlp_kernel(const float* __restrict__ node_attr,
                     const float* __restrict__ edge_attr,
                     const int*   __restrict__ eidx,
                     const float* __restrict__ b1,
                     const float* __restrict__ b2,
                     const float* __restrict__ gamma,
                     const float* __restrict__ beta,
                     float*       __restrict__ out) {
    extern __shared__ char smem[];
    const uint32_t sb = smem_u32(smem);
    const int tid = threadIdx.x;
    const int wid = tid >> 5;
    const int lid = tid & 31;
    const int rg  = wid & 1;          // 2 row groups of 32
    const int cg  = wid >> 1;         // 4 col groups
    const int e0  = blockIdx.x * TILE_M;
    const int valid = min(TILE_M, NE - e0);

    const int* sidx = eidx;
    const int* ridx = eidx + NE;

    float* b1s  = (float*)(smem + OFF_PB1);
    float* b2s  = (float*)(smem + OFF_PB2);
    float* gams = (float*)(smem + OFF_PG);
    float* bets = (float*)(smem + OFF_PBT);
    float* pS   = (float*)(smem + OFF_LNS);
    float* pQ   = (float*)(smem + OFF_LNQ);
    float* muA  = (float*)(smem + OFF_MU);
    float* rsA  = (float*)(smem + OFF_RS);
    b1s[tid] = b1[tid];
    if (tid < 128) { b2s[tid] = b2[tid]; gams[tid] = gamma[tid]; bets[tid] = beta[tid]; }

    // ---- staged gather: chunk kc = cols [(kc&1)*64, +64) of source kc>>1 ----
    // per chunk: 512 tasks (64 rows x 8 segs), 2 per thread, 8 f32 each
    float4 st[4];
    auto gather_ld = [&](int kc) {
        #pragma unroll
        for (int i = 0; i < 2; i++) {
            int task = tid + (i << 8);
            int r = task >> 3, seg = task & 7;
            int e = e0 + r;  if (e >= NE) e = NE - 1;
            int off = ((kc & 1) << 6) + (seg << 3);
            const float* src;
            if (kc < 2)      src = node_attr + (size_t)sidx[e] * 128 + off;
            else if (kc < 4) src = node_attr + (size_t)ridx[e] * 128 + off;
            else             src = edge_attr + (size_t)e * 128 + off;
            st[2 * i]     = ((const float4*)src)[0];
            st[2 * i + 1] = ((const float4*)src)[1];
        }
    };
    auto gather_st = [&](int buf) {
        #pragma unroll
        for (int i = 0; i < 2; i++) {
            int task = tid + (i << 8);
            int r = task >> 3, seg = task & 7;
            float4 x0 = st[2 * i], x1 = st[2 * i + 1];
            uint4 p = make_uint4(packh2(x0.x, x0.y), packh2(x0.z, x0.w),
                                 packh2(x1.x, x1.y), packh2(x1.z, x1.w));
            uint32_t o = (uint32_t)(buf * 8192 + r * 128 + ((seg ^ (r & 7)) << 4));
            *(uint4*)(smem + o) = p;
        }
    };

    auto copyB1 = [&](int c, int buf) {
        const char* s = (const char*)g_B1h + (size_t)c * 32768;
        uint32_t d = sb + OFF_B1 + (uint32_t)buf * 32768u;
        #pragma unroll
        for (int i = 0; i < 8; i++) {
            int t = (tid + (i << 8)) << 4;
            cpa16(d + t, s + t);
        }
    };
    auto copyB2 = [&](int c, int buf) {
        const char* s = (const char*)g_B2h + (size_t)c * 16384;
        uint32_t d = sb + OFF_B2 + (uint32_t)buf * 16384u;
        #pragma unroll
        for (int i = 0; i < 4; i++) {
            int t = (tid + (i << 8)) << 4;
            cpa16(d + t, s + t);
        }
    };

    // ------------------------------------------------------------------------
    // GEMM1: acc1[2][8][4]  (warp: rows rg*32+[0,32), cols cg*64+[0,64))
    // ------------------------------------------------------------------------
    float acc1[2][8][4];
    #pragma unroll
    for (int a = 0; a < 2; a++)
        #pragma unroll
        for (int b = 0; b < 8; b++)
            #pragma unroll
            for (int c = 0; c < 4; c++) acc1[a][b][c] = 0.0f;

    copyB1(0, 0); CPA_COMMIT();
    copyB1(1, 1); CPA_COMMIT();
    gather_ld(0); gather_st(0);
    gather_ld(1); gather_st(1);

    for (int kc = 0; kc < 6; kc++) {
        if (kc < 4) gather_ld(kc + 2);          // LDGs in flight during MMAs
        CPA_WAIT1();
        __syncthreads();                        // chunk kc (A + B1) visible

        const uint32_t aBase = sb + (uint32_t)((kc & 1) * 8192);
        const uint32_t bBase = sb + OFF_B1 + (uint32_t)((kc & 1) * 32768);

        #pragma unroll
        for (int ks = 0; ks < 4; ks++) {
            uint32_t Ah[2][4];
            #pragma unroll
            for (int mg = 0; mg < 2; mg++) {
                int row = rg * 32 + mg * 16 + (lid & 15);
                int seg = 2 * ks + (lid >> 4);
                ldm4(Ah[mg], aBase + (uint32_t)(row * 128 + ((seg ^ (row & 7)) << 4)));
            }
            uint32_t Bh[4][4];
            #pragma unroll
            for (int g = 0; g < 4; g++) {
                int n = cg * 64 + g * 16 + ((lid >> 4) << 3) + (lid & 7);
                int seg = 2 * ks + ((lid >> 3) & 1);
                ldm4(Bh[g], bBase + (uint32_t)(n * 128 + ((seg ^ (n & 7)) << 4)));
            }
            #pragma unroll
            for (int mg = 0; mg < 2; mg++)
                #pragma unroll
                for (int g = 0; g < 4; g++)
                    #pragma unroll
                    for (int h = 0; h < 2; h++)
                        mma16816(acc1[mg][g * 2 + h], Ah[mg], &Bh[g][2 * h]);
        }
        __syncthreads();                        // buffers reusable
        if (kc < 4)      { gather_st(kc & 1); copyB1(kc + 2, kc & 1); CPA_COMMIT(); }
        else if (kc == 4){ copyB2(0, 0); CPA_COMMIT(); }   // into dead B1 buf0 lower
        else             { copyB2(1, 1); CPA_COMMIT(); }   // into dead B1 buf0 upper
    }

    // ------------------------------------------------------------------------
    // Epilogue 1: h = relu(acc1 + b1) -> fp16 -> A2 image (dead B1 buf1)
    // ------------------------------------------------------------------------
    #pragma unroll
    for (int mg = 0; mg < 2; mg++)
        #pragma unroll
        for (int nt = 0; nt < 8; nt++) {
            int coln = cg * 64 + nt * 8 + 2 * (lid & 3);
            float bb0 = b1s[coln], bb1 = b1s[coln + 1];
            int c = coln >> 6, kk = coln & 63, seg = kk >> 3, ee = kk & 7;
            #pragma unroll
            for (int h = 0; h < 2; h++) {
                int row = rg * 32 + mg * 16 + (lid >> 2) + h * 8;
                float v0 = fmaxf(acc1[mg][nt][2 * h]     + bb0, 0.0f);
                float v1 = fmaxf(acc1[mg][nt][2 * h + 1] + bb1, 0.0f);
                uint32_t o = (uint32_t)(row * 128 + ((seg ^ (row & 7)) << 4) + ee * 2);
                *(uint32_t*)(smem + OFF_A2 + c * 8192 + o) = packh2(v0, v1);
            }
        }

    // ------------------------------------------------------------------------
    // GEMM2: acc2[2][4][4]  (warp: rows rg*32, cols cg*32)
    // ------------------------------------------------------------------------
    float acc2[2][4][4];
    #pragma unroll
    for (int a = 0; a < 2; a++)
        #pragma unroll
        for (int b = 0; b < 4; b++)
            #pragma unroll
            for (int c = 0; c < 4; c++) acc2[a][b][c] = 0.0f;

    for (int kc = 0; kc < 4; kc++) {
        if (kc < 3) CPA_WAIT1(); else CPA_WAIT0();
        __syncthreads();                        // B2[kc] + (kc==0: A2) visible

        const uint32_t aBase = sb + OFF_A2 + (uint32_t)(kc * 8192);
        const uint32_t bBase = sb + OFF_B2 + (uint32_t)((kc & 1) * 16384);

        #pragma unroll
        for (int ks = 0; ks < 4; ks++) {
            uint32_t Ah[2][4];
            #pragma unroll
            for (int mg = 0; mg < 2; mg++) {
                int row = rg * 32 + mg * 16 + (lid & 15);
                int seg = 2 * ks + (lid >> 4);
                ldm4(Ah[mg], aBase + (uint32_t)(row * 128 + ((seg ^ (row & 7)) << 4)));
            }
            uint32_t Bh[2][4];
            #pragma unroll
            for (int g = 0; g < 2; g++) {
                int n = cg * 32 + g * 16 + ((lid >> 4) << 3) + (lid & 7);
                int seg = 2 * ks + ((lid >> 3) & 1);
                ldm4(Bh[g], bBase + (uint32_t)(n * 128 + ((seg ^ (n & 7)) << 4)));
            }
            #pragma unroll
            for (int mg = 0; mg < 2; mg++)
                #pragma unroll
                for (int g = 0; g < 2; g++)
                    #pragma unroll
                    for (int h = 0; h < 2; h++)
                        mma16816(acc2[mg][g * 2 + h], Ah[mg], &Bh[g][2 * h]);
        }
        __syncthreads();
        if (kc < 2) { copyB2(kc + 2, kc & 1); CPA_COMMIT(); }
    }

    // ------------------------------------------------------------------------
    // Epilogue 2: LayerNorm fully in registers (shfl quad-reduce + 2KB partials)
    // ------------------------------------------------------------------------
    float sred[2][2], qred[2][2];
    #pragma unroll
    for (int mg = 0; mg < 2; mg++)
        #pragma unroll
        for (int h = 0; h < 2; h++) {
            float s = 0.0f, q = 0.0f;
            #pragma unroll
            for (int nt = 0; nt < 4; nt++) {
                int col = cg * 32 + nt * 8 + 2 * (lid & 3);
                float v0 = acc2[mg][nt][2 * h]     + b2s[col];
                float v1 = acc2[mg][nt][2 * h + 1] + b2s[col + 1];
                acc2[mg][nt][2 * h]     = v0;
                acc2[mg][nt][2 * h + 1] = v1;
                s += v0 + v1;  q += v0 * v0 + v1 * v1;
            }
            s += __shfl_xor_sync(0xffffffffu, s, 1);
            q += __shfl_xor_sync(0xffffffffu, q, 1);
            s += __shfl_xor_sync(0xffffffffu, s, 2);
            q += __shfl_xor_sync(0xffffffffu, q, 2);
            sred[mg][h] = s;  qred[mg][h] = q;
        }
    if ((lid & 3) == 0) {
        int rb = rg * 32 + (lid >> 2);
        pS[(rb)      * 4 + cg] = sred[0][0];  pQ[(rb)      * 4 + cg] = qred[0][0];
        pS[(rb + 8)  * 4 + cg] = sred[0][1];  pQ[(rb + 8)  * 4 + cg] = qred[0][1];
        pS[(rb + 16) * 4 + cg] = sred[1][0];  pQ[(rb + 16) * 4 + cg] = qred[1][0];
        pS[(rb + 24) * 4 + cg] = sred[1][1];  pQ[(rb + 24) * 4 + cg] = qred[1][1];
    }
    __syncthreads();
    if (tid < 64) {
        float ss = pS[tid * 4] + pS[tid * 4 + 1] + pS[tid * 4 + 2] + pS[tid * 4 + 3];
        float qq = pQ[tid * 4] + pQ[tid * 4 + 1] + pQ[tid * 4 + 2] + pQ[tid * 4 + 3];
        float mu = ss * (1.0f / 128.0f);
        float var = fmaxf(qq * (1.0f / 128.0f) - mu * mu, 0.0f);
        muA[tid] = mu;
        rsA[tid] = rsqrtf(var + 1e-5f);
    }
    __syncthreads();
    #pragma unroll
    for (int mg = 0; mg < 2; mg++)
        #pragma unroll
        for (int h = 0; h < 2; h++) {
            int row = rg * 32 + mg * 16 + (lid >> 2) + h * 8;
            if (row < valid) {
                float mu = muA[row], rs = rsA[row];
                float* orow = out + (size_t)(e0 + row) * 128;
                #pragma unroll
                for (int nt = 0; nt < 4; nt++) {
                    int col = cg * 32 + nt * 8 + 2 * (lid & 3);
                    float2 o;
                    o.x = (acc2[mg][nt][2 * h]     - mu) * rs * gams[col]     + bets[col];
                    o.y = (acc2[mg][nt][2 * h + 1] - mu) * rs * gams[col + 1] + bets[col + 1];
                    *(float2*)(orow + col) = o;
                }
            }
        }
}

// ============================================================================
// Launch
// ============================================================================
extern "C" void kernel_launch(void* const* d_in, const int* in_sizes, int n_in,
                              void* d_out, int out_size) {
    const float* node_attr = (const float*)d_in[0];
    const float* edge_attr = (const float*)d_in[1];
    const int*   eidx      = (const int*)d_in[2];
    const float* W1        = (const float*)d_in[3];
    const float* b1        = (const float*)d_in[4];
    const float* W2        = (const float*)d_in[5];
    const float* b2        = (const float*)d_in[6];
    const float* gamma     = (const float*)d_in[7];
    const float* beta      = (const float*)d_in[8];
    float* out = (float*)d_out;

    cudaFuncSetAttribute(edge_mlp_kernel,
                         cudaFuncAttributeMaxDynamicSharedMemorySize, SMEM_TOTAL);

    prep_weights_kernel<<<(384 * 256 + 255) / 256, 256>>>(W1, W2);
    edge_mlp_kernel<<<NBLK, 256, SMEM_TOTAL>>>(node_attr, edge_attr, eidx,
                                               b1, b2, gamma, beta, out);
}

// round 13
// speedup vs baseline: 2.6694x; 1.2989x over previous
#include <cuda_runtime.h>
#include <cuda_fp16.h>
#include <stdint.h>

// ============================================================================
// Problem constants
// ============================================================================
#define NE      300000
#define TILE_M  64
#define NBLK    ((NE + TILE_M - 1) / TILE_M)   // 4688

// ============================================================================
// Weight fragments pre-packed in mma.m16n8k16 B-operand register layout
// (prep kernel fills these each launch).
// GEMM1: warp w covers cols [w*32, w*32+32), 24 k-slices of 16.
//   g_B1f[((w*24 + ks)*2 + j)*32 + lane] = uint4 {nt(2j).r0, nt(2j).r1,
//                                                 nt(2j+1).r0, nt(2j+1).r1}
//   where n-tile nt has 8 cols at n0 = w*32 + j*16 + tile*8, and per PTX spec
//   lane t: r0 = B[k0+2q, k0+2q+1][n0 + t/4], r1 = same with k0+8  (q = t%4).
// GEMM2: warp w covers cols [w*16, w*16+16), 16 k-slices.
//   g_B2f[(w*16 + ks)*32 + lane] = uint4 {nt0.r0, nt0.r1, nt1.r0, nt1.r1}
// ============================================================================
__device__ uint4 g_B1f[12288];   // 196608 B == W1 fp16
__device__ uint4 g_B2f[4096];    //  65536 B == W2 fp16

// ============================================================================
// SMEM layout (bytes), 56320 per CTA -> 2 CTAs/SM (regs are the limiter)
//  [0, 16384)      A1 double buffer (2 x 8K = 64 rows x 128B fp16, swizzled)
//  [16384, 49152)  A2 (h) image: 4 chunks x 8K
//  [49152, 53248)  LN partials pS[64*8], pQ[64*8]
//  [53248, 53760)  mu[64], rs[64]
//  [53760, 56320)  params: b1(1K) b2(512) gamma(512) beta(512)
// ============================================================================
#define OFF_A2   16384
#define OFF_LNS  49152
#define OFF_LNQ  51200
#define OFF_MU   53248
#define OFF_RS   53504
#define OFF_PB1  53760
#define OFF_PB2  54784
#define OFF_PG   55296
#define OFF_PBT  55808
#define SMEM_TOTAL 56320

// ============================================================================
// PTX helpers (sm_80-portable only; tcgen05 rejected by this toolchain target)
// ============================================================================
__device__ __forceinline__ uint32_t smem_u32(const void* p) {
    uint32_t a;
    asm("{ .reg .u64 t; cvta.to.shared.u64 t, %1; cvt.u32.u64 %0, t; }" : "=r"(a) : "l"(p));
    return a;
}

__device__ __forceinline__ void ldm4(uint32_t* d, uint32_t a) {
    asm volatile("ldmatrix.sync.aligned.m8n8.x4.shared.b16 {%0,%1,%2,%3}, [%4];"
                 : "=r"(d[0]), "=r"(d[1]), "=r"(d[2]), "=r"(d[3]) : "r"(a));
}

__device__ __forceinline__ void mma16816(float* c, const uint32_t* a,
                                         uint32_t b0, uint32_t b1) {
    asm volatile(
        "mma.sync.aligned.m16n8k16.row.col.f32.f16.f16.f32 "
        "{%0,%1,%2,%3}, {%4,%5,%6,%7}, {%8,%9}, {%0,%1,%2,%3};"
        : "+f"(c[0]), "+f"(c[1]), "+f"(c[2]), "+f"(c[3])
        : "r"(a[0]), "r"(a[1]), "r"(a[2]), "r"(a[3]), "r"(b0), "r"(b1));
}

__device__ __forceinline__ uint32_t packh2(float a, float b) {
    __half2 h = __floats2half2_rn(a, b);
    return *(uint32_t*)&h;
}

// ============================================================================
// Prep kernel: pack W1/W2 into per-thread mma B fragments
// ============================================================================
__global__ void prep_frag_kernel(const float* __restrict__ W1,
                                 const float* __restrict__ W2) {
    int idx = blockIdx.x * blockDim.x + threadIdx.x;
    if (idx < 12288) {
        int lane = idx & 31;
        int r = idx >> 5;
        int j = r & 1;  r >>= 1;
        int ks = r % 24, w = r / 24;
        int q = lane & 3, g = lane >> 2;
        int k0 = ks * 16 + q * 2;
        int n0 = w * 32 + j * 16 + g;
        int n1 = n0 + 8;
        uint4 v;
        v.x = packh2(W1[k0 * 256 + n0],       W1[(k0 + 1) * 256 + n0]);
        v.y = packh2(W1[(k0 + 8) * 256 + n0], W1[(k0 + 9) * 256 + n0]);
        v.z = packh2(W1[k0 * 256 + n1],       W1[(k0 + 1) * 256 + n1]);
        v.w = packh2(W1[(k0 + 8) * 256 + n1], W1[(k0 + 9) * 256 + n1]);
        g_B1f[idx] = v;
    }
    if (idx < 4096) {
        int lane = idx & 31;
        int r = idx >> 5;
        int ks = r & 15, w = r >> 4;
        int q = lane & 3, g = lane >> 2;
        int k0 = ks * 16 + q * 2;
        int n0 = w * 16 + g;
        int n1 = n0 + 8;
        uint4 v;
        v.x = packh2(W2[k0 * 128 + n0],       W2[(k0 + 1) * 128 + n0]);
        v.y = packh2(W2[(k0 + 8) * 128 + n0], W2[(k0 + 9) * 128 + n0]);
        v.z = packh2(W2[k0 * 128 + n1],       W2[(k0 + 1) * 128 + n1]);
        v.w = packh2(W2[(k0 + 8) * 128 + n1], W2[(k0 + 9) * 128 + n1]);
        g_B2f[idx] = v;
    }
}

// ============================================================================
// Main fused kernel. CTA = 64 edges, 256 threads (8 warps), 2 CTAs/SM.
// GEMM1: out 64x256, warp tile 64x32 (warp w owns cols w*32..+32)
// GEMM2: out 64x128, warp tile 64x16
// B operands: direct coalesced LDG.128 of pre-packed fragments (L2-resident).
// ============================================================================
__global__ __launch_bounds__(256, 2)
void edge_mlp_kernel(const float* __restrict__ node_attr,
                     const float* __restrict__ edge_attr,
                     const int*   __restrict__ eidx,
                     const float* __restrict__ b1,
                     const float* __restrict__ b2,
                     const float* __restrict__ gamma,
                     const float* __restrict__ beta,
                     float*       __restrict__ out) {
    extern __shared__ char smem[];
    const uint32_t sb = smem_u32(smem);
    const int tid = threadIdx.x;
    const int wid = tid >> 5;
    const int lid = tid & 31;
    const int e0  = blockIdx.x * TILE_M;
    const int valid = min(TILE_M, NE - e0);

    const int* sidx = eidx;
    const int* ridx = eidx + NE;

    float* b1s  = (float*)(smem + OFF_PB1);
    float* b2s  = (float*)(smem + OFF_PB2);
    float* gams = (float*)(smem + OFF_PG);
    float* bets = (float*)(smem + OFF_PBT);
    float* pS   = (float*)(smem + OFF_LNS);
    float* pQ   = (float*)(smem + OFF_LNQ);
    float* muA  = (float*)(smem + OFF_MU);
    float* rsA  = (float*)(smem + OFF_RS);
    b1s[tid] = b1[tid];
    if (tid < 128) { b2s[tid] = b2[tid]; gams[tid] = gamma[tid]; bets[tid] = beta[tid]; }

    // ---- staged gather: chunk kc = cols [(kc&1)*64, +64) of source kc>>1 ----
    float4 st[4];
    auto gather_ld = [&](int kc) {
        #pragma unroll
        for (int i = 0; i < 2; i++) {
            int task = tid + (i << 8);
            int r = task >> 3, seg = task & 7;
            int e = e0 + r;  if (e >= NE) e = NE - 1;
            int off = ((kc & 1) << 6) + (seg << 3);
            const float* src;
            if (kc < 2)      src = node_attr + (size_t)sidx[e] * 128 + off;
            else if (kc < 4) src = node_attr + (size_t)ridx[e] * 128 + off;
            else             src = edge_attr + (size_t)e * 128 + off;
            st[2 * i]     = ((const float4*)src)[0];
            st[2 * i + 1] = ((const float4*)src)[1];
        }
    };
    auto gather_st = [&](int buf) {
        #pragma unroll
        for (int i = 0; i < 2; i++) {
            int task = tid + (i << 8);
            int r = task >> 3, seg = task & 7;
            float4 x0 = st[2 * i], x1 = st[2 * i + 1];
            uint4 p = make_uint4(packh2(x0.x, x0.y), packh2(x0.z, x0.w),
                                 packh2(x1.x, x1.y), packh2(x1.z, x1.w));
            uint32_t o = (uint32_t)(buf * 8192 + r * 128 + ((seg ^ (r & 7)) << 4));
            *(uint4*)(smem + o) = p;
        }
    };

    // ------------------------------------------------------------------------
    // GEMM1: acc1[4][4][4]  (warp: rows 0..63, cols wid*32..+32)
    // ------------------------------------------------------------------------
    float acc1[4][4][4];
    #pragma unroll
    for (int a = 0; a < 4; a++)
        #pragma unroll
        for (int b = 0; b < 4; b++)
            #pragma unroll
            for (int c = 0; c < 4; c++) acc1[a][b][c] = 0.0f;

    gather_ld(0); gather_st(0);
    gather_ld(1); gather_st(1);
    __syncthreads();

    const uint4* B1f = g_B1f + (size_t)wid * 1536 + lid;  // stride/ks = 64
    uint4 bf0 = B1f[0], bf1 = B1f[32];
    uint4 bn0, bn1;

    for (int kc = 0; kc < 6; kc++) {
        if (kc < 4) gather_ld(kc + 2);          // edge LDGs fly during MMAs
        const uint32_t aBase = sb + (uint32_t)((kc & 1) * 8192);

        #pragma unroll
        for (int ks = 0; ks < 4; ks++) {
            int ksg = kc * 4 + ks;
            if (ksg < 23) { bn0 = B1f[(ksg + 1) * 64]; bn1 = B1f[(ksg + 1) * 64 + 32]; }
            uint32_t Ah[4][4];
            #pragma unroll
            for (int mg = 0; mg < 4; mg++) {
                int row = mg * 16 + (lid & 15);
                int seg = 2 * ks + (lid >> 4);
                ldm4(Ah[mg], aBase + (uint32_t)(row * 128 + ((seg ^ (row & 7)) << 4)));
            }
            #pragma unroll
            for (int mg = 0; mg < 4; mg++) {
                mma16816(acc1[mg][0], Ah[mg], bf0.x, bf0.y);
                mma16816(acc1[mg][1], Ah[mg], bf0.z, bf0.w);
                mma16816(acc1[mg][2], Ah[mg], bf1.x, bf1.y);
                mma16816(acc1[mg][3], Ah[mg], bf1.z, bf1.w);
            }
            bf0 = bn0;  bf1 = bn1;
        }
        __syncthreads();                        // all warps done with chunk kc
        if (kc < 4) gather_st((kc + 2) & 1);    // refill buffer (same parity as chunk kc+2)
    }

    // prefetch first GEMM2 B fragment early
    const uint4* B2f = g_B2f + (size_t)wid * 512 + lid;   // stride/ks = 32
    uint4 b2c = B2f[0], b2n;

    // ------------------------------------------------------------------------
    // Epilogue 1: h = relu(acc1 + b1) -> fp16 -> A2 image
    // value (mg,nt,c): row = mg*16 + (lid>>2) + (c>>1)*8,
    //                  col = wid*32 + nt*8 + 2*(lid&3) + (c&1)
    // ------------------------------------------------------------------------
    #pragma unroll
    for (int mg = 0; mg < 4; mg++)
        #pragma unroll
        for (int nt = 0; nt < 4; nt++) {
            int col = wid * 32 + nt * 8 + 2 * (lid & 3);
            float bb0 = b1s[col], bb1 = b1s[col + 1];
            int c = col >> 6, kk = col & 63, seg = kk >> 3, ee = kk & 7;
            #pragma unroll
            for (int h = 0; h < 2; h++) {
                int row = mg * 16 + (lid >> 2) + h * 8;
                float v0 = fmaxf(acc1[mg][nt][2 * h]     + bb0, 0.0f);
                float v1 = fmaxf(acc1[mg][nt][2 * h + 1] + bb1, 0.0f);
                uint32_t o = (uint32_t)(row * 128 + ((seg ^ (row & 7)) << 4) + ee * 2);
                *(uint32_t*)(smem + OFF_A2 + c * 8192 + o) = packh2(v0, v1);
            }
        }
    __syncthreads();                            // h visible to all warps

    // ------------------------------------------------------------------------
    // GEMM2: acc2[4][2][4]  (warp: rows 0..63, cols wid*16..+16), no syncs
    // ------------------------------------------------------------------------
    float acc2[4][2][4];
    #pragma unroll
    for (int a = 0; a < 4; a++)
        #pragma unroll
        for (int b = 0; b < 2; b++)
            #pragma unroll
            for (int c = 0; c < 4; c++) acc2[a][b][c] = 0.0f;

    for (int kc = 0; kc < 4; kc++) {
        const uint32_t aBase = sb + OFF_A2 + (uint32_t)(kc * 8192);
        #pragma unroll
        for (int ks = 0; ks < 4; ks++) {
            int ksg = kc * 4 + ks;
            if (ksg < 15) b2n = B2f[(ksg + 1) * 32];
            uint32_t Ah[4][4];
            #pragma unroll
            for (int mg = 0; mg < 4; mg++) {
                int row = mg * 16 + (lid & 15);
                int seg = 2 * ks + (lid >> 4);
                ldm4(Ah[mg], aBase + (uint32_t)(row * 128 + ((seg ^ (row & 7)) << 4)));
            }
            #pragma unroll
            for (int mg = 0; mg < 4; mg++) {
                mma16816(acc2[mg][0], Ah[mg], b2c.x, b2c.y);
                mma16816(acc2[mg][1], Ah[mg], b2c.z, b2c.w);
            }
            b2c = b2n;
        }
    }

    // ------------------------------------------------------------------------
    // Epilogue 2: LayerNorm (quad shfl + cross-warp smem partials) -> store
    // ------------------------------------------------------------------------
    #pragma unroll
    for (int mg = 0; mg < 4; mg++)
        #pragma unroll
        for (int h = 0; h < 2; h++) {
            int row = mg * 16 + (lid >> 2) + h * 8;
            float s = 0.0f, q = 0.0f;
            #pragma unroll
            for (int nt = 0; nt < 2; nt++) {
                int col = wid * 16 + nt * 8 + 2 * (lid & 3);
                float v0 = acc2[mg][nt][2 * h]     + b2s[col];
                float v1 = acc2[mg][nt][2 * h + 1] + b2s[col + 1];
                acc2[mg][nt][2 * h]     = v0;
                acc2[mg][nt][2 * h + 1] = v1;
                s += v0 + v1;  q += v0 * v0 + v1 * v1;
            }
            s += __shfl_xor_sync(0xffffffffu, s, 1);
            q += __shfl_xor_sync(0xffffffffu, q, 1);
            s += __shfl_xor_sync(0xffffffffu, s, 2);
            q += __shfl_xor_sync(0xffffffffu, q, 2);
            if ((lid & 3) == 0) { pS[row * 8 + wid] = s; pQ[row * 8 + wid] = q; }
        }
    __syncthreads();
    if (tid < 64) {
        const float* ps = pS + tid * 8;
        const float* pq = pQ + tid * 8;
        float ss = 0.0f, qq = 0.0f;
        #pragma unroll
        for (int w = 0; w < 8; w++) { ss += ps[w]; qq += pq[w]; }
        float mu = ss * (1.0f / 128.0f);
        float var = fmaxf(qq * (1.0f / 128.0f) - mu * mu, 0.0f);
        muA[tid] = mu;
        rsA[tid] = rsqrtf(var + 1e-5f);
    }
    __syncthreads();
    #pragma unroll
    for (int mg = 0; mg < 4; mg++)
        #pragma unroll
        for (int h = 0; h < 2; h++) {
            int row = mg * 16 + (lid >> 2) + h * 8;
            if (row < valid) {
                float mu = muA[row], rs = rsA[row];
                float* orow = out + (size_t)(e0 + row) * 128;
                #pragma unroll
                for (int nt = 0; nt < 2; nt++) {
                    int col = wid * 16 + nt * 8 + 2 * (lid & 3);
                    float2 o;
                    o.x = (acc2[mg][nt][2 * h]     - mu) * rs * gams[col]     + bets[col];
                    o.y = (acc2[mg][nt][2 * h + 1] - mu) * rs * gams[col + 1] + bets[col + 1];
                    *(float2*)(orow + col) = o;
                }
            }
        }
}

// ============================================================================
// Launch
// ============================================================================
extern "C" void kernel_launch(void* const* d_in, const int* in_sizes, int n_in,
                              void* d_out, int out_size) {
    const float* node_attr = (const float*)d_in[0];
    const float* edge_attr = (const float*)d_in[1];
    const int*   eidx      = (const int*)d_in[2];
    const float* W1        = (const float*)d_in[3];
    const float* b1        = (const float*)d_in[4];
    const float* W2        = (const float*)d_in[5];
    const float* b2        = (const float*)d_in[6];
    const float* gamma     = (const float*)d_in[7];
    const float* beta      = (const float*)d_in[8];
    float* out = (float*)d_out;

    cudaFuncSetAttribute(edge_mlp_kernel,
                         cudaFuncAttributeMaxDynamicSharedMemorySize, SMEM_TOTAL);

    prep_frag_kernel<<<48, 256>>>(W1, W2);
    edge_mlp_kernel<<<NBLK, 256, SMEM_TOTAL>>>(node_attr, edge_attr, eidx,
                                               b1, b2, gamma, beta, out);
}

// round 17
// speedup vs baseline: 3.0851x; 1.1557x over previous
#include <cuda_runtime.h>
#include <cuda_fp16.h>
#include <stdint.h>

// ============================================================================
// Problem constants
// ============================================================================
#define NE      300000
#define TILE_M  64
#define NBLK    ((NE + TILE_M - 1) / TILE_M)   // 4688

// ============================================================================
// Weight fragments pre-packed in mma.m16n8k16 B-operand register layout
// (prep kernel fills these each launch).  Layouts identical to R13.
// ============================================================================
__device__ uint4 g_B1f[12288];   // 196608 B == W1 fp16
__device__ uint4 g_B2f[4096];    //  65536 B == W2 fp16

// ============================================================================
// SMEM layout (bytes), 89088 per CTA -> 2 CTAs/SM (regs are the limiter)
//  [0, 49152)      A1 full image: 6 chunks x 8K (64 rows x 128B fp16, swizzled)
//  [49152, 81920)  A2 (h) image: 4 chunks x 8K
//  [81920, 86016)  LN partials pS[64*8], pQ[64*8]
//  [86016, 86528)  mu[64], rs[64]
//  [86528, 89088)  params: b1(1K) b2(512) gamma(512) beta(512)
// ============================================================================
#define OFF_A2   49152
#define OFF_LNS  81920
#define OFF_LNQ  83968
#define OFF_MU   86016
#define OFF_RS   86272
#define OFF_PB1  86528
#define OFF_PB2  87552
#define OFF_PG   88064
#define OFF_PBT  88576
#define SMEM_TOTAL 89088

// ============================================================================
// PTX helpers (sm_80-portable only; tcgen05 rejected by this toolchain target)
// ============================================================================
__device__ __forceinline__ uint32_t smem_u32(const void* p) {
    uint32_t a;
    asm("{ .reg .u64 t; cvta.to.shared.u64 t, %1; cvt.u32.u64 %0, t; }" : "=r"(a) : "l"(p));
    return a;
}

__device__ __forceinline__ void ldm4(uint32_t* d, uint32_t a) {
    asm volatile("ldmatrix.sync.aligned.m8n8.x4.shared.b16 {%0,%1,%2,%3}, [%4];"
                 : "=r"(d[0]), "=r"(d[1]), "=r"(d[2]), "=r"(d[3]) : "r"(a));
}

__device__ __forceinline__ void mma16816(float* c, const uint32_t* a,
                                         uint32_t b0, uint32_t b1) {
    asm volatile(
        "mma.sync.aligned.m16n8k16.row.col.f32.f16.f16.f32 "
        "{%0,%1,%2,%3}, {%4,%5,%6,%7}, {%8,%9}, {%0,%1,%2,%3};"
        : "+f"(c[0]), "+f"(c[1]), "+f"(c[2]), "+f"(c[3])
        : "r"(a[0]), "r"(a[1]), "r"(a[2]), "r"(a[3]), "r"(b0), "r"(b1));
}

__device__ __forceinline__ uint32_t packh2(float a, float b) {
    __half2 h = __floats2half2_rn(a, b);
    return *(uint32_t*)&h;
}

// ============================================================================
// Prep kernel: pack W1/W2 into per-thread mma B fragments (same as R13)
// ============================================================================
__global__ void prep_frag_kernel(const float* __restrict__ W1,
                                 const float* __restrict__ W2) {
    int idx = blockIdx.x * blockDim.x + threadIdx.x;
    if (idx < 12288) {
        int lane = idx & 31;
        int r = idx >> 5;
        int j = r & 1;  r >>= 1;
        int ks = r % 24, w = r / 24;
        int q = lane & 3, g = lane >> 2;
        int k0 = ks * 16 + q * 2;
        int n0 = w * 32 + j * 16 + g;
        int n1 = n0 + 8;
        uint4 v;
        v.x = packh2(W1[k0 * 256 + n0],       W1[(k0 + 1) * 256 + n0]);
        v.y = packh2(W1[(k0 + 8) * 256 + n0], W1[(k0 + 9) * 256 + n0]);
        v.z = packh2(W1[k0 * 256 + n1],       W1[(k0 + 1) * 256 + n1]);
        v.w = packh2(W1[(k0 + 8) * 256 + n1], W1[(k0 + 9) * 256 + n1]);
        g_B1f[idx] = v;
    }
    if (idx < 4096) {
        int lane = idx & 31;
        int r = idx >> 5;
        int ks = r & 15, w = r >> 4;
        int q = lane & 3, g = lane >> 2;
        int k0 = ks * 16 + q * 2;
        int n0 = w * 16 + g;
        int n1 = n0 + 8;
        uint4 v;
        v.x = packh2(W2[k0 * 128 + n0],       W2[(k0 + 1) * 128 + n0]);
        v.y = packh2(W2[(k0 + 8) * 128 + n0], W2[(k0 + 9) * 128 + n0]);
        v.z = packh2(W2[k0 * 128 + n1],       W2[(k0 + 1) * 128 + n1]);
        v.w = packh2(W2[(k0 + 8) * 128 + n1], W2[(k0 + 9) * 128 + n1]);
        g_B2f[idx] = v;
    }
}

// ============================================================================
// Main fused kernel. CTA = 64 edges, 256 threads (8 warps), 2 CTAs/SM.
// GEMM1: out 64x256, warp tile 64x32; GEMM2: out 64x128, warp tile 64x16.
// A1 fully resident (48KB) -> barrier-free 24-ks GEMM1 mainloop.
// B operands: coalesced LDG.128 of pre-packed fragments (L2-resident).
// ============================================================================
__global__ __launch_bounds__(256, 2)
void edge_mlp_kernel(const float* __restrict__ node_attr,
                     const float* __restrict__ edge_attr,
                     const int*   __restrict__ eidx,
                     const float* __restrict__ b1,
                     const float* __restrict__ b2,
                     const float* __restrict__ gamma,
                     const float* __restrict__ beta,
                     float*       __restrict__ out) {
    extern __shared__ char smem[];
    const uint32_t sb = smem_u32(smem);
    const int tid = threadIdx.x;
    const int wid = tid >> 5;
    const int lid = tid & 31;
    const int e0  = blockIdx.x * TILE_M;
    const int valid = min(TILE_M, NE - e0);

    const int* sidx = eidx;
    const int* ridx = eidx + NE;

    float* b1s  = (float*)(smem + OFF_PB1);
    float* b2s  = (float*)(smem + OFF_PB2);
    float* gams = (float*)(smem + OFF_PG);
    float* bets = (float*)(smem + OFF_PBT);
    float* pS   = (float*)(smem + OFF_LNS);
    float* pQ   = (float*)(smem + OFF_LNQ);
    float* muA  = (float*)(smem + OFF_MU);
    float* rsA  = (float*)(smem + OFF_RS);
    b1s[tid] = b1[tid];
    if (tid < 128) { b2s[tid] = b2[tid]; gams[tid] = gamma[tid]; bets[tid] = beta[tid]; }

    // ---- gather: chunk kc = cols [(kc&1)*64, +64) of source kc>>1 ----------
    // chunk = 64 rows x 64 cols; per thread 2 tasks x 8 floats
    auto gather_ld = [&](int kc, float4* st) {
        #pragma unroll
        for (int i = 0; i < 2; i++) {
            int task = tid + (i << 8);
            int r = task >> 3, seg = task & 7;
            int e = e0 + r;  if (e >= NE) e = NE - 1;
            int off = ((kc & 1) << 6) + (seg << 3);
            const float* src;
            if (kc < 2)      src = node_attr + (size_t)sidx[e] * 128 + off;
            else if (kc < 4) src = node_attr + (size_t)ridx[e] * 128 + off;
            else             src = edge_attr + (size_t)e * 128 + off;
            st[2 * i]     = ((const float4*)src)[0];
            st[2 * i + 1] = ((const float4*)src)[1];
        }
    };
    auto gather_st = [&](int kc, const float4* st) {
        #pragma unroll
        for (int i = 0; i < 2; i++) {
            int task = tid + (i << 8);
            int r = task >> 3, seg = task & 7;
            float4 x0 = st[2 * i], x1 = st[2 * i + 1];
            uint4 p = make_uint4(packh2(x0.x, x0.y), packh2(x0.z, x0.w),
                                 packh2(x1.x, x1.y), packh2(x1.z, x1.w));
            uint32_t o = (uint32_t)(kc * 8192 + r * 128 + ((seg ^ (r & 7)) << 4));
            *(uint4*)(smem + o) = p;
        }
    };

    // ---- fill full A1 image (6 chunks), rolling 2-deep register staging ----
    {
        float4 sA[4], sB[4];
        gather_ld(0, sA); gather_ld(1, sB);
        gather_st(0, sA); gather_ld(2, sA);
        gather_st(1, sB); gather_ld(3, sB);
        gather_st(2, sA); gather_ld(4, sA);
        gather_st(3, sB); gather_ld(5, sB);
        gather_st(4, sA); gather_st(5, sB);
    }
    __syncthreads();                            // A1 fully visible — ONLY sync before GEMM1

    // ------------------------------------------------------------------------
    // GEMM1: acc1[4][4][4]  (warp: rows 0..63, cols wid*32..+32), barrier-free
    // ------------------------------------------------------------------------
    float acc1[4][4][4];
    #pragma unroll
    for (int a = 0; a < 4; a++)
        #pragma unroll
        for (int b = 0; b < 4; b++)
            #pragma unroll
            for (int c = 0; c < 4; c++) acc1[a][b][c] = 0.0f;

    const uint4* B1f = g_B1f + (size_t)wid * 1536 + lid;  // stride per ks = 64
    uint4 bf0 = B1f[0], bf1 = B1f[32];

    #pragma unroll
    for (int ksg = 0; ksg < 24; ksg++) {
        uint4 bn0, bn1;
        if (ksg < 23) { bn0 = B1f[(ksg + 1) * 64]; bn1 = B1f[(ksg + 1) * 64 + 32]; }
        const uint32_t aBase = sb + (uint32_t)((ksg >> 2) * 8192);
        const int ks = ksg & 3;
        uint32_t Ah[4][4];
        #pragma unroll
        for (int mg = 0; mg < 4; mg++) {
            int row = mg * 16 + (lid & 15);
            int seg = 2 * ks + (lid >> 4);
            ldm4(Ah[mg], aBase + (uint32_t)(row * 128 + ((seg ^ (row & 7)) << 4)));
        }
        #pragma unroll
        for (int mg = 0; mg < 4; mg++) {
            mma16816(acc1[mg][0], Ah[mg], bf0.x, bf0.y);
            mma16816(acc1[mg][1], Ah[mg], bf0.z, bf0.w);
            mma16816(acc1[mg][2], Ah[mg], bf1.x, bf1.y);
            mma16816(acc1[mg][3], Ah[mg], bf1.z, bf1.w);
        }
        bf0 = bn0;  bf1 = bn1;
    }

    // prefetch first GEMM2 B fragment early
    const uint4* B2f = g_B2f + (size_t)wid * 512 + lid;   // stride per ks = 32
    uint4 b2c = B2f[0], b2n;

    // ------------------------------------------------------------------------
    // Epilogue 1: h = relu(acc1 + b1) -> fp16 -> A2 image
    // ------------------------------------------------------------------------
    #pragma unroll
    for (int mg = 0; mg < 4; mg++)
        #pragma unroll
        for (int nt = 0; nt < 4; nt++) {
            int col = wid * 32 + nt * 8 + 2 * (lid & 3);
            float bb0 = b1s[col], bb1 = b1s[col + 1];
            int c = col >> 6, kk = col & 63, seg = kk >> 3, ee = kk & 7;
            #pragma unroll
            for (int h = 0; h < 2; h++) {
                int row = mg * 16 + (lid >> 2) + h * 8;
                float v0 = fmaxf(acc1[mg][nt][2 * h]     + bb0, 0.0f);
                float v1 = fmaxf(acc1[mg][nt][2 * h + 1] + bb1, 0.0f);
                uint32_t o = (uint32_t)(row * 128 + ((seg ^ (row & 7)) << 4) + ee * 2);
                *(uint32_t*)(smem + OFF_A2 + c * 8192 + o) = packh2(v0, v1);
            }
        }
    __syncthreads();                            // h visible to all warps

    // ------------------------------------------------------------------------
    // GEMM2: acc2[4][2][4]  (warp: rows 0..63, cols wid*16..+16), barrier-free
    // ------------------------------------------------------------------------
    float acc2[4][2][4];
    #pragma unroll
    for (int a = 0; a < 4; a++)
        #pragma unroll
        for (int b = 0; b < 2; b++)
            #pragma unroll
            for (int c = 0; c < 4; c++) acc2[a][b][c] = 0.0f;

    #pragma unroll
    for (int ksg = 0; ksg < 16; ksg++) {
        if (ksg < 15) b2n = B2f[(ksg + 1) * 32];
        const uint32_t aBase = sb + OFF_A2 + (uint32_t)((ksg >> 2) * 8192);
        const int ks = ksg & 3;
        uint32_t Ah[4][4];
        #pragma unroll
        for (int mg = 0; mg < 4; mg++) {
            int row = mg * 16 + (lid & 15);
            int seg = 2 * ks + (lid >> 4);
            ldm4(Ah[mg], aBase + (uint32_t)(row * 128 + ((seg ^ (row & 7)) << 4)));
        }
        #pragma unroll
        for (int mg = 0; mg < 4; mg++) {
            mma16816(acc2[mg][0], Ah[mg], b2c.x, b2c.y);
            mma16816(acc2[mg][1], Ah[mg], b2c.z, b2c.w);
        }
        b2c = b2n;
    }

    // ------------------------------------------------------------------------
    // Epilogue 2: LayerNorm (quad shfl + cross-warp smem partials) -> store
    // ------------------------------------------------------------------------
    #pragma unroll
    for (int mg = 0; mg < 4; mg++)
        #pragma unroll
        for (int h = 0; h < 2; h++) {
            int row = mg * 16 + (lid >> 2) + h * 8;
            float s = 0.0f, q = 0.0f;
            #pragma unroll
            for (int nt = 0; nt < 2; nt++) {
                int col = wid * 16 + nt * 8 + 2 * (lid & 3);
                float v0 = acc2[mg][nt][2 * h]     + b2s[col];
                float v1 = acc2[mg][nt][2 * h + 1] + b2s[col + 1];
                acc2[mg][nt][2 * h]     = v0;
                acc2[mg][nt][2 * h + 1] = v1;
                s += v0 + v1;  q += v0 * v0 + v1 * v1;
            }
            s += __shfl_xor_sync(0xffffffffu, s, 1);
            q += __shfl_xor_sync(0xffffffffu, q, 1);
            s += __shfl_xor_sync(0xffffffffu, s, 2);
            q += __shfl_xor_sync(0xffffffffu, q, 2);
            if ((lid & 3) == 0) { pS[row * 8 + wid] = s; pQ[row * 8 + wid] = q; }
        }
    __syncthreads();
    if (tid < 64) {
        const float* ps = pS + tid * 8;
        const float* pq = pQ + tid * 8;
        float ss = 0.0f, qq = 0.0f;
        #pragma unroll
        for (int w = 0; w < 8; w++) { ss += ps[w]; qq += pq[w]; }
        float mu = ss * (1.0f / 128.0f);
        float var = fmaxf(qq * (1.0f / 128.0f) - mu * mu, 0.0f);
        muA[tid] = mu;
        rsA[tid] = rsqrtf(var + 1e-5f);
    }
    __syncthreads();
    #pragma unroll
    for (int mg = 0; mg < 4; mg++)
        #pragma unroll
        for (int h = 0; h < 2; h++) {
            int row = mg * 16 + (lid >> 2) + h * 8;
            if (row < valid) {
                float mu = muA[row], rs = rsA[row];
                float* orow = out + (size_t)(e0 + row) * 128;
                #pragma unroll
                for (int nt = 0; nt < 2; nt++) {
                    int col = wid * 16 + nt * 8 + 2 * (lid & 3);
                    float2 o;
                    o.x = (acc2[mg][nt][2 * h]     - mu) * rs * gams[col]     + bets[col];
                    o.y = (acc2[mg][nt][2 * h + 1] - mu) * rs * gams[col + 1] + bets[col + 1];
                    *(float2*)(orow + col) = o;
                }
            }
        }
}

// ============================================================================
// Launch
// ============================================================================
extern "C" void kernel_launch(void* const* d_in, const int* in_sizes, int n_in,
                              void* d_out, int out_size) {
    const float* node_attr = (const float*)d_in[0];
    const float* edge_attr = (const float*)d_in[1];
    const int*   eidx      = (const int*)d_in[2];
    const float* W1        = (const float*)d_in[3];
    const float* b1        = (const float*)d_in[4];
    const float* W2        = (const float*)d_in[5];
    const float* b2        = (const float*)d_in[6];
    const float* gamma     = (const float*)d_in[7];
    const float* beta      = (const float*)d_in[8];
    float* out = (float*)d_out;

    cudaFuncSetAttribute(edge_mlp_kernel,
                         cudaFuncAttributeMaxDynamicSharedMemorySize, SMEM_TOTAL);

    prep_frag_kernel<<<48, 256>>>(W1, W2);
    edge_mlp_kernel<<<NBLK, 256, SMEM_TOTAL>>>(node_attr, edge_attr, eidx,
                                               b1, b2, gamma, beta, out);
}